// round 1
// baseline (speedup 1.0000x reference)
#include <cuda_runtime.h>
#include <math.h>

#define DIMX      128
#define NCODE     512
#define M_TILE    64
#define NTHREADS  256
#define CHUNK     64
#define XS_STRIDE 129
#define CB_STRIDE 129
#define LG_STRIDE 516
#define EPSF      1e-6f

// smem layout (floats):
//   xs:    M_TILE * XS_STRIDE            = 8256
//   cbs:   CHUNK  * CB_STRIDE            = 8256
//   lg:    M_TILE * LG_STRIDE            = 33024
//   norms: M_TILE                        = 64
#define XS_OFF   0
#define CB_OFF   (XS_OFF + M_TILE * XS_STRIDE)
#define LG_OFF   (CB_OFF + CHUNK * CB_STRIDE)
#define NRM_OFF  (LG_OFF + M_TILE * LG_STRIDE)
#define SMEM_FLOATS (NRM_OFF + M_TILE)
#define SMEM_BYTES  (SMEM_FLOATS * 4)

__global__ __launch_bounds__(NTHREADS, 1)
void gumbel_vq_kernel(const float* __restrict__ x,
                      const float* __restrict__ mask,
                      const float* __restrict__ codebook,
                      const float* __restrict__ noise,
                      float* __restrict__ q_out,
                      float* __restrict__ enc_out,
                      float* __restrict__ idx_out)
{
    extern __shared__ float smem[];
    float* xs   = smem + XS_OFF;
    float* cbs  = smem + CB_OFF;
    float* lg   = smem + LG_OFF;
    float* nrm  = smem + NRM_OFF;

    const int tid  = threadIdx.x;
    const int wid  = tid >> 5;
    const int lane = tid & 31;
    const int tr   = tid >> 4;   // 0..15
    const int tc   = tid & 15;   // 0..15
    const int row0 = blockIdx.x * M_TILE;

    // ---------- Phase A: load x tile (with mask nudge) ----------
    for (int idx = tid; idx < M_TILE * DIMX; idx += NTHREADS) {
        int r = idx >> 7;
        int k = idx & 127;
        float m  = mask[row0 + r];
        float xv = x[(size_t)(row0 + r) * DIMX + k];
        xs[r * XS_STRIDE + k] = xv + (1.0f - m) * EPSF;
    }
    __syncthreads();

    // row norms: warp w handles rows [w*8, w*8+8)
    for (int rr = 0; rr < 8; rr++) {
        int r = wid * 8 + rr;
        float s = 0.0f;
        #pragma unroll
        for (int k = lane; k < DIMX; k += 32) {
            float v = xs[r * XS_STRIDE + k];
            s += v * v;
        }
        #pragma unroll
        for (int off = 16; off > 0; off >>= 1)
            s += __shfl_down_sync(0xffffffffu, s, off);
        if (lane == 0)
            nrm[r] = fmaxf(sqrtf(s), EPSF);
    }
    __syncthreads();

    // normalize (IEEE divide to match reference x / norm)
    for (int idx = tid; idx < M_TILE * DIMX; idx += NTHREADS) {
        int r = idx >> 7;
        int k = idx & 127;
        xs[r * XS_STRIDE + k] = xs[r * XS_STRIDE + k] / nrm[r];
    }
    __syncthreads();

    // ---------- Phase B: GEMM1  S = Xn @ CB^T, store distances ----------
    for (int cc = 0; cc < NCODE; cc += CHUNK) {
        for (int idx = tid; idx < CHUNK * DIMX; idx += NTHREADS) {
            int c = idx >> 7;
            int k = idx & 127;
            cbs[c * CB_STRIDE + k] = codebook[(size_t)(cc + c) * DIMX + k];
        }
        __syncthreads();

        float acc[4][4];
        #pragma unroll
        for (int i = 0; i < 4; i++)
            #pragma unroll
            for (int j = 0; j < 4; j++)
                acc[i][j] = 0.0f;

        #pragma unroll 8
        for (int k = 0; k < DIMX; k++) {
            float a[4], b[4];
            #pragma unroll
            for (int i = 0; i < 4; i++)
                a[i] = xs[(tr + 16 * i) * XS_STRIDE + k];
            #pragma unroll
            for (int j = 0; j < 4; j++)
                b[j] = cbs[(tc + 16 * j) * CB_STRIDE + k];
            #pragma unroll
            for (int i = 0; i < 4; i++)
                #pragma unroll
                for (int j = 0; j < 4; j++)
                    acc[i][j] = fmaf(a[i], b[j], acc[i][j]);
        }

        // distances, same association as reference: (1 - 2*ab) + 1
        #pragma unroll
        for (int i = 0; i < 4; i++)
            #pragma unroll
            for (int j = 0; j < 4; j++) {
                float d = (1.0f - 2.0f * acc[i][j]) + 1.0f;
                lg[(tr + 16 * i) * LG_STRIDE + cc + tc + 16 * j] = d;
            }
        __syncthreads();
    }

    // ---------- Phase C: argmin + gumbel softmax (warp per row) ----------
    for (int rr = 0; rr < 8; rr++) {
        int r = wid * 8 + rr;
        size_t grow = (size_t)(row0 + r);

        // pass 1: argmin over distances (first-wins), logits = -d + noise, row max
        float mind = 3.402823466e+38f;
        int   mini = 0;
        float maxl = -3.402823466e+38f;
        #pragma unroll
        for (int c = lane; c < NCODE; c += 32) {
            float d = lg[r * LG_STRIDE + c];
            if (d < mind) { mind = d; mini = c; }
            float l = noise[grow * NCODE + c] - d;
            lg[r * LG_STRIDE + c] = l;
            maxl = fmaxf(maxl, l);
        }
        #pragma unroll
        for (int off = 16; off > 0; off >>= 1) {
            float d2 = __shfl_down_sync(0xffffffffu, mind, off);
            int   i2 = __shfl_down_sync(0xffffffffu, mini, off);
            if (d2 < mind || (d2 == mind && i2 < mini)) { mind = d2; mini = i2; }
            maxl = fmaxf(maxl, __shfl_down_sync(0xffffffffu, maxl, off));
        }
        maxl = __shfl_sync(0xffffffffu, maxl, 0);

        // pass 2: exp and sum
        float s = 0.0f;
        #pragma unroll
        for (int c = lane; c < NCODE; c += 32) {
            float e = expf(lg[r * LG_STRIDE + c] - maxl);
            lg[r * LG_STRIDE + c] = e;
            s += e;
        }
        #pragma unroll
        for (int off = 16; off > 0; off >>= 1)
            s += __shfl_down_sync(0xffffffffu, s, off);
        s = __shfl_sync(0xffffffffu, s, 0);

        // pass 3: probabilities -> smem (for GEMM2) + gmem encodings
        #pragma unroll
        for (int c = lane; c < NCODE; c += 32) {
            float p = lg[r * LG_STRIDE + c] / s;
            lg[r * LG_STRIDE + c] = p;
            enc_out[grow * NCODE + c] = p;
        }
        if (lane == 0)
            idx_out[grow] = (float)mini;
    }
    __syncthreads();

    // ---------- Phase D: GEMM2  Q = P @ CB ----------
    float out[4][8];
    #pragma unroll
    for (int i = 0; i < 4; i++)
        #pragma unroll
        for (int j = 0; j < 8; j++)
            out[i][j] = 0.0f;

    for (int cc = 0; cc < NCODE; cc += CHUNK) {
        for (int idx = tid; idx < CHUNK * DIMX; idx += NTHREADS) {
            int c = idx >> 7;
            int k = idx & 127;
            cbs[c * CB_STRIDE + k] = codebook[(size_t)(cc + c) * DIMX + k];
        }
        __syncthreads();

        #pragma unroll 4
        for (int c = 0; c < CHUNK; c++) {
            float p[4], b[8];
            #pragma unroll
            for (int i = 0; i < 4; i++)
                p[i] = lg[(tr + 16 * i) * LG_STRIDE + cc + c];
            #pragma unroll
            for (int j = 0; j < 8; j++)
                b[j] = cbs[c * CB_STRIDE + tc + 16 * j];
            #pragma unroll
            for (int i = 0; i < 4; i++)
                #pragma unroll
                for (int j = 0; j < 8; j++)
                    out[i][j] = fmaf(p[i], b[j], out[i][j]);
        }
        __syncthreads();
    }

    #pragma unroll
    for (int i = 0; i < 4; i++) {
        size_t grow = (size_t)(row0 + tr + 16 * i);
        #pragma unroll
        for (int j = 0; j < 8; j++)
            q_out[grow * DIMX + tc + 16 * j] = out[i][j];
    }
}

extern "C" void kernel_launch(void* const* d_in, const int* in_sizes, int n_in,
                              void* d_out, int out_size)
{
    const float* x        = (const float*)d_in[0];
    const float* mask     = (const float*)d_in[1];
    const float* codebook = (const float*)d_in[2];
    const float* noise    = (const float*)d_in[3];

    const int n = in_sizes[0] / DIMX;   // 131072

    float* q_out   = (float*)d_out;
    float* enc_out = q_out + (size_t)n * DIMX;
    float* idx_out = enc_out + (size_t)n * NCODE;

    cudaFuncSetAttribute(gumbel_vq_kernel,
                         cudaFuncAttributeMaxDynamicSharedMemorySize,
                         SMEM_BYTES);

    int grid = n / M_TILE;
    gumbel_vq_kernel<<<grid, NTHREADS, SMEM_BYTES>>>(
        x, mask, codebook, noise, q_out, enc_out, idx_out);
}

// round 2
// speedup vs baseline: 1.4137x; 1.4137x over previous
#include <cuda_runtime.h>
#include <math.h>
#include <stdint.h>

#define DIMX     128
#define NCODE    512
#define MTILE    32
#define NTHREADS 256
#define EPSF     1e-6f

#define XS  132   // stride for xraw/xh/xl
#define CBS 132   // stride for GEMM1 cb chunk (32 codes x 128 k)
#define CTS 36    // stride for GEMM2 cbT chunk (128 feat x 32 codes)
#define PS  516   // stride for p (32 x 512)

// region1: phase1 = xraw(32*132) xh(32*132) xl(32*132) = 12672 ; phase2 = p(32*516)=16512
#define R1_FLOATS 16512
#define XRAW_OFF  0
#define XH_OFF    4224
#define XL_OFF    8448
// region2: phase1 = cb1h(4224) cb1l(4224) = 8448 ; phaseC scratch (512) ; phase2 = cbth(4608) cbtl(4608) = 9216
#define R2_FLOATS 9216
#define SMEM_FLOATS (R1_FLOATS + R2_FLOATS + 32)
#define SMEM_BYTES  (SMEM_FLOATS * 4)

__device__ __forceinline__ uint32_t f2tf(float x) {
    uint32_t r;
    asm("cvt.rna.tf32.f32 %0, %1;" : "=r"(r) : "f"(x));
    return r;
}

__device__ __forceinline__ void mma8(float* d,
                                     uint32_t a0, uint32_t a1, uint32_t a2, uint32_t a3,
                                     uint32_t b0, uint32_t b1) {
    asm volatile(
        "mma.sync.aligned.m16n8k8.row.col.f32.tf32.tf32.f32 "
        "{%0,%1,%2,%3},{%4,%5,%6,%7},{%8,%9},{%0,%1,%2,%3};"
        : "+f"(d[0]), "+f"(d[1]), "+f"(d[2]), "+f"(d[3])
        : "r"(a0), "r"(a1), "r"(a2), "r"(a3), "r"(b0), "r"(b1));
}

__global__ __launch_bounds__(NTHREADS, 2)
void gumbel_vq_tc_kernel(const float* __restrict__ x,
                         const float* __restrict__ mask,
                         const float* __restrict__ codebook,
                         const float* __restrict__ noise,
                         float* __restrict__ q_out,
                         float* __restrict__ enc_out,
                         float* __restrict__ idx_out)
{
    extern __shared__ float smem[];
    float* r1   = smem;                 // xraw/xh/xl then p
    float* r2   = smem + R1_FLOATS;     // cb chunks / reduction scratch
    float* nrm  = smem + R1_FLOATS + R2_FLOATS;

    float* xraw = r1 + XRAW_OFF;
    float* xh   = r1 + XH_OFF;
    float* xl   = r1 + XL_OFF;
    float* pS   = r1;                   // 32 x PS, alias after GEMM1

    float* cb1h = r2;
    float* cb1l = r2 + 4224;
    float* cbth = r2;
    float* cbtl = r2 + 4608;
    // phase-C scratch (region2 is otherwise idle there)
    float* redD = r2;          // 32 rows * 4 warps
    float* redI = r2 + 128;
    float* redM = r2 + 256;
    float* redS = r2 + 384;

    const int tid  = threadIdx.x;
    const int wid  = tid >> 5;
    const int lane = tid & 31;
    const int wr   = wid >> 2;     // 0..1 : row group (16 rows)
    const int wc   = wid & 3;      // 0..3 : column group
    const int lq   = lane >> 2;    // 0..7
    const int lr   = lane & 3;     // 0..3
    const int row0 = blockIdx.x * MTILE;
    const int ar   = wr * 16 + lq; // this thread's base row (also +8)

    // ================= Phase A: load x, normalize, split hi/lo =================
    #pragma unroll
    for (int j = 0; j < 16; j++) {
        int e = tid + 256 * j;
        int r = e >> 7, k = e & 127;
        float m  = mask[row0 + r];
        float xv = x[(size_t)(row0 + r) * DIMX + k];
        xraw[r * XS + k] = xv + (1.0f - m) * EPSF;
    }
    __syncthreads();

    {   // row norms: warp wid handles rows 4*wid .. 4*wid+3, 8 lanes per row
        int rrow = wid * 4 + (lane >> 3);
        float acc = 0.0f;
        #pragma unroll
        for (int j = 0; j < 16; j++) {
            float v = xraw[rrow * XS + (lane & 7) + 8 * j];
            acc += v * v;
        }
        acc += __shfl_xor_sync(0xffffffffu, acc, 1);
        acc += __shfl_xor_sync(0xffffffffu, acc, 2);
        acc += __shfl_xor_sync(0xffffffffu, acc, 4);
        if ((lane & 7) == 0)
            nrm[rrow] = fmaxf(sqrtf(acc), EPSF);
    }
    __syncthreads();

    #pragma unroll
    for (int j = 0; j < 16; j++) {
        int e = tid + 256 * j;
        int r = e >> 7, k = e & 127;
        float v = xraw[r * XS + k] / nrm[r];
        uint32_t hi = f2tf(v);
        float lof = v - __uint_as_float(hi);
        xh[r * XS + k] = __uint_as_float(hi);
        xl[r * XS + k] = __uint_as_float(f2tf(lof));
    }
    __syncthreads();

    // ================= Phase B: GEMM1 scores = Xn @ CB^T (3xTF32) =================
    float s[16][4];
    #pragma unroll
    for (int f = 0; f < 16; f++)
        #pragma unroll
        for (int e = 0; e < 4; e++)
            s[f][e] = 0.0f;

    const int bb = wc * 8 + lq;   // code row within 32-code chunk for B frags

    #pragma unroll
    for (int ch = 0; ch < 16; ch++) {
        // stage 32 codes, hi/lo split
        const float* cbsrc = codebook + (size_t)ch * 32 * DIMX;
        #pragma unroll
        for (int j = 0; j < 16; j++) {
            int e = tid + 256 * j;
            int c = e >> 7, k = e & 127;
            float v = cbsrc[e];
            uint32_t hi = f2tf(v);
            float lof = v - __uint_as_float(hi);
            cb1h[c * CBS + k] = __uint_as_float(hi);
            cb1l[c * CBS + k] = __uint_as_float(f2tf(lof));
        }
        __syncthreads();

        #pragma unroll
        for (int ks = 0; ks < 16; ks++) {
            int k0 = ks * 8;
            uint32_t ah0 = __float_as_uint(xh[ar * XS + k0 + lr]);
            uint32_t ah1 = __float_as_uint(xh[(ar + 8) * XS + k0 + lr]);
            uint32_t ah2 = __float_as_uint(xh[ar * XS + k0 + 4 + lr]);
            uint32_t ah3 = __float_as_uint(xh[(ar + 8) * XS + k0 + 4 + lr]);
            uint32_t al0 = __float_as_uint(xl[ar * XS + k0 + lr]);
            uint32_t al1 = __float_as_uint(xl[(ar + 8) * XS + k0 + lr]);
            uint32_t al2 = __float_as_uint(xl[ar * XS + k0 + 4 + lr]);
            uint32_t al3 = __float_as_uint(xl[(ar + 8) * XS + k0 + 4 + lr]);
            uint32_t bh0 = __float_as_uint(cb1h[bb * CBS + k0 + lr]);
            uint32_t bh1 = __float_as_uint(cb1h[bb * CBS + k0 + 4 + lr]);
            uint32_t bl0 = __float_as_uint(cb1l[bb * CBS + k0 + lr]);
            uint32_t bl1 = __float_as_uint(cb1l[bb * CBS + k0 + 4 + lr]);
            mma8(s[ch], ah0, ah1, ah2, ah3, bh0, bh1);
            mma8(s[ch], ah0, ah1, ah2, ah3, bl0, bl1);
            mma8(s[ch], al0, al1, al2, al3, bh0, bh1);
        }
        __syncthreads();
    }

    // ================= Phase C: distances -> gumbel softmax -> P =================
    float mind[2], maxl[2], sum2[2], inv[2];
    int   mini[2];
    #pragma unroll
    for (int r = 0; r < 2; r++) {
        mind[r] = 3.402823466e+38f;
        mini[r] = 0;
        maxl[r] = -3.402823466e+38f;
    }

    // C1: logits = noise - dist, per-warp argmin/max over this warp's 128 cols
    #pragma unroll
    for (int ch = 0; ch < 16; ch++) {
        int cbase = ch * 32 + wc * 8 + 2 * lr;
        #pragma unroll
        for (int r = 0; r < 2; r++) {
            int grow = row0 + ar + 8 * r;
            float2 nz = *reinterpret_cast<const float2*>(
                noise + (size_t)grow * NCODE + cbase);
            float d0 = (1.0f - 2.0f * s[ch][2 * r]) + 1.0f;
            float d1 = (1.0f - 2.0f * s[ch][2 * r + 1]) + 1.0f;
            if (d0 < mind[r]) { mind[r] = d0; mini[r] = cbase; }
            if (d1 < mind[r]) { mind[r] = d1; mini[r] = cbase + 1; }
            float l0 = nz.x - d0;
            float l1 = nz.y - d1;
            maxl[r] = fmaxf(maxl[r], fmaxf(l0, l1));
            s[ch][2 * r]     = l0;
            s[ch][2 * r + 1] = l1;
        }
    }
    // reduce across the 4 lanes sharing a row
    #pragma unroll
    for (int r = 0; r < 2; r++) {
        #pragma unroll
        for (int off = 1; off < 4; off <<= 1) {
            float od = __shfl_xor_sync(0xffffffffu, mind[r], off);
            int   oi = __shfl_xor_sync(0xffffffffu, mini[r], off);
            if (od < mind[r] || (od == mind[r] && oi < mini[r])) {
                mind[r] = od; mini[r] = oi;
            }
            maxl[r] = fmaxf(maxl[r], __shfl_xor_sync(0xffffffffu, maxl[r], off));
        }
    }
    // publish per-warp partials (region2 is free here)
    if (lr == 0) {
        #pragma unroll
        for (int r = 0; r < 2; r++) {
            int lrow = ar + 8 * r;
            redD[lrow * 4 + wc] = mind[r];
            redI[lrow * 4 + wc] = (float)mini[r];
            redM[lrow * 4 + wc] = maxl[r];
        }
    }
    __syncthreads();
    // C2: combine across the 4 column-warps
    #pragma unroll
    for (int r = 0; r < 2; r++) {
        int lrow = ar + 8 * r;
        float gd = redD[lrow * 4 + 0];
        int   gi = (int)redI[lrow * 4 + 0];
        float gm = redM[lrow * 4 + 0];
        #pragma unroll
        for (int w2 = 1; w2 < 4; w2++) {
            float od = redD[lrow * 4 + w2];
            int   oi = (int)redI[lrow * 4 + w2];
            if (od < gd || (od == gd && oi < gi)) { gd = od; gi = oi; }
            gm = fmaxf(gm, redM[lrow * 4 + w2]);
        }
        mini[r] = gi;
        maxl[r] = gm;
        sum2[r] = 0.0f;
    }
    // exp + per-warp sum
    #pragma unroll
    for (int ch = 0; ch < 16; ch++) {
        #pragma unroll
        for (int r = 0; r < 2; r++) {
            float e0 = __expf(s[ch][2 * r]     - maxl[r]);
            float e1 = __expf(s[ch][2 * r + 1] - maxl[r]);
            s[ch][2 * r]     = e0;
            s[ch][2 * r + 1] = e1;
            sum2[r] += e0 + e1;
        }
    }
    #pragma unroll
    for (int r = 0; r < 2; r++) {
        sum2[r] += __shfl_xor_sync(0xffffffffu, sum2[r], 1);
        sum2[r] += __shfl_xor_sync(0xffffffffu, sum2[r], 2);
    }
    if (lr == 0) {
        redS[(ar) * 4 + wc]     = sum2[0];
        redS[(ar + 8) * 4 + wc] = sum2[1];
    }
    __syncthreads();
    #pragma unroll
    for (int r = 0; r < 2; r++) {
        int lrow = ar + 8 * r;
        float t = redS[lrow * 4 + 0] + redS[lrow * 4 + 1]
                + redS[lrow * 4 + 2] + redS[lrow * 4 + 3];
        inv[r] = 1.0f / t;
    }
    __syncthreads();   // region1 (xh/xl) & region2 scratch now dead -> reuse

    // probs -> p smem + enc_out ; indices
    #pragma unroll
    for (int ch = 0; ch < 16; ch++) {
        int cbase = ch * 32 + wc * 8 + 2 * lr;
        #pragma unroll
        for (int r = 0; r < 2; r++) {
            int lrow = ar + 8 * r;
            float p0 = s[ch][2 * r]     * inv[r];
            float p1 = s[ch][2 * r + 1] * inv[r];
            *reinterpret_cast<float2*>(pS + lrow * PS + cbase) = make_float2(p0, p1);
            *reinterpret_cast<float2*>(enc_out + (size_t)(row0 + lrow) * NCODE + cbase)
                = make_float2(p0, p1);
        }
    }
    if (lr == 0 && wc == 0) {
        idx_out[row0 + ar]     = (float)mini[0];
        idx_out[row0 + ar + 8] = (float)mini[1];
    }
    __syncthreads();

    // ================= Phase D: GEMM2  Q = P @ CB (3xTF32) =================
    float q[4][4];
    #pragma unroll
    for (int nf = 0; nf < 4; nf++)
        #pragma unroll
        for (int e = 0; e < 4; e++)
            q[nf][e] = 0.0f;

    for (int kc = 0; kc < 16; kc++) {
        // stage cbT chunk (32 codes, transposed, hi/lo)
        {
            int cl = tid >> 3;               // code within chunk
            const float* src = codebook + (size_t)(kc * 32 + cl) * DIMX;
            #pragma unroll
            for (int i = 0; i < 16; i++) {
                int k = (tid & 7) + 8 * i;   // feature index
                float v = src[k];
                uint32_t hi = f2tf(v);
                float lof = v - __uint_as_float(hi);
                cbth[k * CTS + cl] = __uint_as_float(hi);
                cbtl[k * CTS + cl] = __uint_as_float(f2tf(lof));
            }
        }
        __syncthreads();

        #pragma unroll
        for (int ks = 0; ks < 4; ks++) {
            int kk = kc * 32 + ks * 8;   // global code index for A
            int kl = ks * 8;             // local code index for B
            float av0 = pS[ar * PS + kk + lr];
            float av1 = pS[(ar + 8) * PS + kk + lr];
            float av2 = pS[ar * PS + kk + 4 + lr];
            float av3 = pS[(ar + 8) * PS + kk + 4 + lr];
            uint32_t ah0 = f2tf(av0), ah1 = f2tf(av1), ah2 = f2tf(av2), ah3 = f2tf(av3);
            uint32_t al0 = f2tf(av0 - __uint_as_float(ah0));
            uint32_t al1 = f2tf(av1 - __uint_as_float(ah1));
            uint32_t al2 = f2tf(av2 - __uint_as_float(ah2));
            uint32_t al3 = f2tf(av3 - __uint_as_float(ah3));
            #pragma unroll
            for (int nf = 0; nf < 4; nf++) {
                int nb = wc * 32 + nf * 8 + lq;   // feature row in cbT
                uint32_t bh0 = __float_as_uint(cbth[nb * CTS + kl + lr]);
                uint32_t bh1 = __float_as_uint(cbth[nb * CTS + kl + 4 + lr]);
                uint32_t bl0 = __float_as_uint(cbtl[nb * CTS + kl + lr]);
                uint32_t bl1 = __float_as_uint(cbtl[nb * CTS + kl + 4 + lr]);
                mma8(q[nf], ah0, ah1, ah2, ah3, bh0, bh1);
                mma8(q[nf], ah0, ah1, ah2, ah3, bl0, bl1);
                mma8(q[nf], al0, al1, al2, al3, bh0, bh1);
            }
        }
        __syncthreads();
    }

    // store Q
    #pragma unroll
    for (int nf = 0; nf < 4; nf++) {
        int gcol = wc * 32 + nf * 8 + 2 * lr;
        #pragma unroll
        for (int r = 0; r < 2; r++) {
            int grow = row0 + ar + 8 * r;
            *reinterpret_cast<float2*>(q_out + (size_t)grow * DIMX + gcol)
                = make_float2(q[nf][2 * r], q[nf][2 * r + 1]);
        }
    }
}

extern "C" void kernel_launch(void* const* d_in, const int* in_sizes, int n_in,
                              void* d_out, int out_size)
{
    const float* x        = (const float*)d_in[0];
    const float* mask     = (const float*)d_in[1];
    const float* codebook = (const float*)d_in[2];
    const float* noise    = (const float*)d_in[3];

    const int n = in_sizes[0] / DIMX;   // 131072

    float* q_out   = (float*)d_out;
    float* enc_out = q_out + (size_t)n * DIMX;
    float* idx_out = enc_out + (size_t)n * NCODE;

    cudaFuncSetAttribute(gumbel_vq_tc_kernel,
                         cudaFuncAttributeMaxDynamicSharedMemorySize,
                         SMEM_BYTES);

    int grid = n / MTILE;   // 4096
    gumbel_vq_tc_kernel<<<grid, NTHREADS, SMEM_BYTES>>>(
        x, mask, codebook, noise, q_out, enc_out, idx_out);
}

// round 3
// speedup vs baseline: 2.8929x; 2.0464x over previous
#include <cuda_runtime.h>
#include <cuda_fp16.h>
#include <stdint.h>
#include <math.h>

#define DIMX     128
#define NCODE    512
#define MTILE    32
#define NTHREADS 256
#define EPSF     1e-6f

#define XS1 136   // halves: x fp16 row stride
#define CBS 136   // halves: codebook chunk row stride (64 codes x 128)
#define PS2 520   // halves: P row stride (32 x 512)

// half-offsets in dynamic smem
#define P16H_OFF  0
#define P16L_OFF  16640
#define XS16H_OFF 0           // overlays p16 region (disjoint in time)
#define XS16L_OFF 4352
#define CBH_OFF   33280
#define CBL_OFF   41984
#define SCR_OFF   50688       // 512 floats of reduction scratch
#define SMEM_HALVES (SCR_OFF + 1024)
#define SMEM_BYTES  (SMEM_HALVES * 2)

__device__ __half cbh_g[NCODE * DIMX];
__device__ __half cbl_g[NCODE * DIMX];

__device__ __forceinline__ void split2(float v, __half& h, __half& l) {
    h = __float2half_rn(v);
    l = __float2half_rn(v - __half2float(h));
}

__device__ __forceinline__ void mma16(float* d,
                                      uint32_t a0, uint32_t a1, uint32_t a2, uint32_t a3,
                                      uint32_t b0, uint32_t b1) {
    asm volatile(
        "mma.sync.aligned.m16n8k16.row.col.f32.f16.f16.f32 "
        "{%0,%1,%2,%3},{%4,%5,%6,%7},{%8,%9},{%0,%1,%2,%3};"
        : "+f"(d[0]), "+f"(d[1]), "+f"(d[2]), "+f"(d[3])
        : "r"(a0), "r"(a1), "r"(a2), "r"(a3), "r"(b0), "r"(b1));
}

__device__ __forceinline__ void ldsm_x4(uint32_t& r0, uint32_t& r1, uint32_t& r2, uint32_t& r3,
                                        uint32_t addr) {
    asm volatile("ldmatrix.sync.aligned.m8n8.x4.shared.b16 {%0,%1,%2,%3},[%4];"
                 : "=r"(r0), "=r"(r1), "=r"(r2), "=r"(r3) : "r"(addr));
}
__device__ __forceinline__ void ldsm_x2(uint32_t& r0, uint32_t& r1, uint32_t addr) {
    asm volatile("ldmatrix.sync.aligned.m8n8.x2.shared.b16 {%0,%1},[%2];"
                 : "=r"(r0), "=r"(r1) : "r"(addr));
}
__device__ __forceinline__ void ldsm_x2t(uint32_t& r0, uint32_t& r1, uint32_t addr) {
    asm volatile("ldmatrix.sync.aligned.m8n8.x2.trans.shared.b16 {%0,%1},[%2];"
                 : "=r"(r0), "=r"(r1) : "r"(addr));
}

__global__ void cb_split_kernel(const float* __restrict__ cb) {
    int i = (blockIdx.x * 256 + threadIdx.x) * 4;
    float4 v = *(const float4*)(cb + i);
    __half h0, l0, h1, l1, h2, l2, h3, l3;
    split2(v.x, h0, l0); split2(v.y, h1, l1);
    split2(v.z, h2, l2); split2(v.w, h3, l3);
    *(half2*)(cbh_g + i)     = __halves2half2(h0, h1);
    *(half2*)(cbh_g + i + 2) = __halves2half2(h2, h3);
    *(half2*)(cbl_g + i)     = __halves2half2(l0, l1);
    *(half2*)(cbl_g + i + 2) = __halves2half2(l2, l3);
}

__global__ __launch_bounds__(NTHREADS, 2)
void gvq_main(const float* __restrict__ x,
              const float* __restrict__ mask,
              const float* __restrict__ noise,
              float* __restrict__ q_out,
              float* __restrict__ enc_out,
              float* __restrict__ idx_out)
{
    extern __shared__ __half sm[];
    __half* p16h = sm + P16H_OFF;
    __half* p16l = sm + P16L_OFF;
    __half* xs_h = sm + XS16H_OFF;
    __half* xs_l = sm + XS16L_OFF;
    __half* cb_h = sm + CBH_OFF;
    __half* cb_l = sm + CBL_OFF;
    float* scr  = (float*)(sm + SCR_OFF);
    float* redD = scr;
    float* redI = scr + 128;
    float* redM = scr + 256;
    float* redS = scr + 384;

    const int tid  = threadIdx.x;
    const int wid  = tid >> 5;
    const int lane = tid & 31;
    const int wr   = wid >> 2;
    const int wc   = wid & 3;
    const int lq   = lane >> 2;
    const int lr   = lane & 3;
    const int row0 = blockIdx.x * MTILE;
    const int ar   = wr * 16 + lq;
    const int ar0  = wr * 16;

    const uint32_t smem_u32 = (uint32_t)__cvta_generic_to_shared(sm);
    const uint32_t cbl_delta = (CBL_OFF - CBH_OFF) * 2;

    // ================= Phase A: load x, mask-nudge, normalize, fp16-split =================
    {
        int arow = wid * 4 + (lane >> 3);
        int u    = lane & 7;
        float mv = mask[row0 + arow];
        float nudge = (1.0f - mv) * EPSF;
        const float4* xp = (const float4*)(x + (size_t)(row0 + arow) * DIMX + u * 16);
        float v[16];
        float acc = 0.0f;
        #pragma unroll
        for (int j = 0; j < 4; j++) {
            float4 t = xp[j];
            v[4*j+0] = t.x + nudge; v[4*j+1] = t.y + nudge;
            v[4*j+2] = t.z + nudge; v[4*j+3] = t.w + nudge;
        }
        #pragma unroll
        for (int j = 0; j < 16; j++) acc += v[j] * v[j];
        acc += __shfl_xor_sync(0xffffffffu, acc, 1);
        acc += __shfl_xor_sync(0xffffffffu, acc, 2);
        acc += __shfl_xor_sync(0xffffffffu, acc, 4);
        float nr = fmaxf(sqrtf(acc), EPSF);
        #pragma unroll
        for (int j = 0; j < 8; j++) {
            float a0 = v[2*j]   / nr;
            float a1 = v[2*j+1] / nr;
            __half h0, l0, h1, l1;
            split2(a0, h0, l0);
            split2(a1, h1, l1);
            *(half2*)&xs_h[arow * XS1 + u * 16 + 2*j] = __halves2half2(h0, h1);
            *(half2*)&xs_l[arow * XS1 + u * 16 + 2*j] = __halves2half2(l0, l1);
        }
    }

    // ================= Phase B: GEMM1  scores = Xn @ CB^T (fp16 2-split) =================
    float s[16][4];
    #pragma unroll
    for (int m = 0; m < 16; m++)
        #pragma unroll
        for (int e = 0; e < 4; e++)
            s[m][e] = 0.0f;

    const uint32_t a1h_base = smem_u32 + XS16H_OFF * 2
                            + (ar0 + (lane & 15)) * (XS1 * 2) + ((lane >> 4) & 1) * 16;
    const uint32_t a1l_base = a1h_base + (XS16L_OFF - XS16H_OFF) * 2;
    const uint32_t b1_base  = smem_u32 + CBH_OFF * 2
                            + (wc * 8 + (lane & 7)) * (CBS * 2) + (lane & 8) * 2;

    for (int ch = 0; ch < 8; ch++) {
        __syncthreads();
        {   // stage 64 pre-split codes: pure uint4 copy
            const uint4* sh = (const uint4*)(cbh_g + ch * 64 * DIMX);
            const uint4* sl = (const uint4*)(cbl_g + ch * 64 * DIMX);
            #pragma unroll
            for (int j = 0; j < 4; j++) {
                int f  = tid + 256 * j;     // 1024 uint4 total
                int c  = f >> 4;
                int kq = f & 15;
                *(uint4*)&cb_h[c * CBS + kq * 8] = sh[f];
                *(uint4*)&cb_l[c * CBS + kq * 8] = sl[f];
            }
        }
        __syncthreads();

        #pragma unroll
        for (int ks = 0; ks < 8; ks++) {
            uint32_t ah0, ah1, ah2, ah3, al0, al1, al2, al3;
            ldsm_x4(ah0, ah1, ah2, ah3, a1h_base + ks * 32);
            ldsm_x4(al0, al1, al2, al3, a1l_base + ks * 32);
            #pragma unroll
            for (int ci = 0; ci < 2; ci++) {
                uint32_t baddr = b1_base + ci * (32 * CBS * 2) + ks * 32;
                uint32_t bh0, bh1, bl0, bl1;
                ldsm_x2(bh0, bh1, baddr);
                ldsm_x2(bl0, bl1, baddr + cbl_delta);
                float* d = s[ch * 2 + ci];
                mma16(d, ah0, ah1, ah2, ah3, bh0, bh1);
                mma16(d, ah0, ah1, ah2, ah3, bl0, bl1);
                mma16(d, al0, al1, al2, al3, bh0, bh1);
            }
        }
    }

    // ================= Phase C: distances -> argmin -> gumbel softmax =================
    float mind[2], maxl[2], sum2[2], inv[2];
    int   mini[2];
    #pragma unroll
    for (int r = 0; r < 2; r++) {
        mind[r] = 3.402823466e+38f;
        mini[r] = 0;
        maxl[r] = -3.402823466e+38f;
    }

    #pragma unroll
    for (int m = 0; m < 16; m++) {
        int cbase = m * 32 + wc * 8 + 2 * lr;
        #pragma unroll
        for (int r = 0; r < 2; r++) {
            int grow = row0 + ar + 8 * r;
            float2 nz = *(const float2*)(noise + (size_t)grow * NCODE + cbase);
            float d0 = (1.0f - 2.0f * s[m][2*r])     + 1.0f;
            float d1 = (1.0f - 2.0f * s[m][2*r + 1]) + 1.0f;
            if (d0 < mind[r]) { mind[r] = d0; mini[r] = cbase; }
            if (d1 < mind[r]) { mind[r] = d1; mini[r] = cbase + 1; }
            float l0 = nz.x - d0;
            float l1 = nz.y - d1;
            maxl[r] = fmaxf(maxl[r], fmaxf(l0, l1));
            s[m][2*r]     = l0;
            s[m][2*r + 1] = l1;
        }
    }
    #pragma unroll
    for (int r = 0; r < 2; r++) {
        #pragma unroll
        for (int off = 1; off < 4; off <<= 1) {
            float od = __shfl_xor_sync(0xffffffffu, mind[r], off);
            int   oi = __shfl_xor_sync(0xffffffffu, mini[r], off);
            if (od < mind[r] || (od == mind[r] && oi < mini[r])) { mind[r] = od; mini[r] = oi; }
            maxl[r] = fmaxf(maxl[r], __shfl_xor_sync(0xffffffffu, maxl[r], off));
        }
    }
    if (lr == 0) {
        #pragma unroll
        for (int r = 0; r < 2; r++) {
            int lrow = ar + 8 * r;
            redD[lrow * 4 + wc] = mind[r];
            redI[lrow * 4 + wc] = (float)mini[r];
            redM[lrow * 4 + wc] = maxl[r];
        }
    }
    __syncthreads();
    #pragma unroll
    for (int r = 0; r < 2; r++) {
        int lrow = ar + 8 * r;
        float gd = redD[lrow * 4 + 0];
        int   gi = (int)redI[lrow * 4 + 0];
        float gm = redM[lrow * 4 + 0];
        #pragma unroll
        for (int w2 = 1; w2 < 4; w2++) {
            float od = redD[lrow * 4 + w2];
            int   oi = (int)redI[lrow * 4 + w2];
            if (od < gd || (od == gd && oi < gi)) { gd = od; gi = oi; }
            gm = fmaxf(gm, redM[lrow * 4 + w2]);
        }
        mini[r] = gi;
        maxl[r] = gm;
        sum2[r] = 0.0f;
    }
    #pragma unroll
    for (int m = 0; m < 16; m++) {
        #pragma unroll
        for (int r = 0; r < 2; r++) {
            float e0 = __expf(s[m][2*r]     - maxl[r]);
            float e1 = __expf(s[m][2*r + 1] - maxl[r]);
            s[m][2*r]     = e0;
            s[m][2*r + 1] = e1;
            sum2[r] += e0 + e1;
        }
    }
    #pragma unroll
    for (int r = 0; r < 2; r++) {
        sum2[r] += __shfl_xor_sync(0xffffffffu, sum2[r], 1);
        sum2[r] += __shfl_xor_sync(0xffffffffu, sum2[r], 2);
    }
    if (lr == 0) {
        redS[ar * 4 + wc]       = sum2[0];
        redS[(ar + 8) * 4 + wc] = sum2[1];
    }
    __syncthreads();
    #pragma unroll
    for (int r = 0; r < 2; r++) {
        int lrow = ar + 8 * r;
        float t = redS[lrow * 4 + 0] + redS[lrow * 4 + 1]
                + redS[lrow * 4 + 2] + redS[lrow * 4 + 3];
        inv[r] = 1.0f / t;
    }
    __syncthreads();   // GEMM1 regions dead; safe to write p16 (overlays xs16)

    #pragma unroll
    for (int m = 0; m < 16; m++) {
        int cbase = m * 32 + wc * 8 + 2 * lr;
        #pragma unroll
        for (int r = 0; r < 2; r++) {
            int lrow = ar + 8 * r;
            float p0 = s[m][2*r]     * inv[r];
            float p1 = s[m][2*r + 1] * inv[r];
            __half h0, l0, h1, l1;
            split2(p0, h0, l0);
            split2(p1, h1, l1);
            *(half2*)&p16h[lrow * PS2 + cbase] = __halves2half2(h0, h1);
            *(half2*)&p16l[lrow * PS2 + cbase] = __halves2half2(l0, l1);
            *(float2*)(enc_out + (size_t)(row0 + lrow) * NCODE + cbase)
                = make_float2(p0, p1);
        }
    }
    if (lr == 0 && wc == 0) {
        idx_out[row0 + ar]     = (float)mini[0];
        idx_out[row0 + ar + 8] = (float)mini[1];
    }

    // ================= Phase D: GEMM2  Q = P @ CB (fp16 2-split) =================
    float q[4][4];
    #pragma unroll
    for (int nf = 0; nf < 4; nf++)
        #pragma unroll
        for (int e = 0; e < 4; e++)
            q[nf][e] = 0.0f;

    const uint32_t a2h_base = smem_u32 + P16H_OFF * 2
                            + (ar0 + (lane & 15)) * (PS2 * 2) + ((lane >> 4) & 1) * 16;
    const uint32_t a2l_base = a2h_base + (P16L_OFF - P16H_OFF) * 2;
    const uint32_t b2_base  = smem_u32 + CBH_OFF * 2
                            + (lane & 15) * (CBS * 2) + (wc * 32) * 2;

    for (int kc = 0; kc < 8; kc++) {
        __syncthreads();
        {   // stage 64 pre-split codes (natural layout; trans happens in ldmatrix)
            const uint4* sh = (const uint4*)(cbh_g + kc * 64 * DIMX);
            const uint4* sl = (const uint4*)(cbl_g + kc * 64 * DIMX);
            #pragma unroll
            for (int j = 0; j < 4; j++) {
                int f  = tid + 256 * j;
                int c  = f >> 4;
                int kq = f & 15;
                *(uint4*)&cb_h[c * CBS + kq * 8] = sh[f];
                *(uint4*)&cb_l[c * CBS + kq * 8] = sl[f];
            }
        }
        __syncthreads();

        #pragma unroll
        for (int ks = 0; ks < 4; ks++) {
            uint32_t ah0, ah1, ah2, ah3, al0, al1, al2, al3;
            uint32_t aoff = (kc * 64 + ks * 16) * 2;
            ldsm_x4(ah0, ah1, ah2, ah3, a2h_base + aoff);
            ldsm_x4(al0, al1, al2, al3, a2l_base + aoff);
            #pragma unroll
            for (int nf = 0; nf < 4; nf++) {
                uint32_t baddr = b2_base + ks * (16 * CBS * 2) + nf * 16;
                uint32_t bh0, bh1, bl0, bl1;
                ldsm_x2t(bh0, bh1, baddr);
                ldsm_x2t(bl0, bl1, baddr + cbl_delta);
                mma16(q[nf], ah0, ah1, ah2, ah3, bh0, bh1);
                mma16(q[nf], ah0, ah1, ah2, ah3, bl0, bl1);
                mma16(q[nf], al0, al1, al2, al3, bh0, bh1);
            }
        }
    }

    #pragma unroll
    for (int nf = 0; nf < 4; nf++) {
        int gcol = wc * 32 + nf * 8 + 2 * lr;
        #pragma unroll
        for (int r = 0; r < 2; r++) {
            int grow = row0 + ar + 8 * r;
            *(float2*)(q_out + (size_t)grow * DIMX + gcol)
                = make_float2(q[nf][2*r], q[nf][2*r + 1]);
        }
    }
}

extern "C" void kernel_launch(void* const* d_in, const int* in_sizes, int n_in,
                              void* d_out, int out_size)
{
    const float* x        = (const float*)d_in[0];
    const float* mask     = (const float*)d_in[1];
    const float* codebook = (const float*)d_in[2];
    const float* noise    = (const float*)d_in[3];

    const int n = in_sizes[0] / DIMX;   // 131072

    float* q_out   = (float*)d_out;
    float* enc_out = q_out + (size_t)n * DIMX;
    float* idx_out = enc_out + (size_t)n * NCODE;

    cb_split_kernel<<<NCODE * DIMX / 1024, 256>>>(codebook);

    cudaFuncSetAttribute(gvq_main,
                         cudaFuncAttributeMaxDynamicSharedMemorySize,
                         SMEM_BYTES);
    gvq_main<<<n / MTILE, NTHREADS, SMEM_BYTES>>>(
        x, mask, noise, q_out, enc_out, idx_out);
}

// round 4
// speedup vs baseline: 3.2067x; 1.1085x over previous
#include <cuda_runtime.h>
#include <cuda_fp16.h>
#include <stdint.h>
#include <math.h>

#define DIMX     128
#define NCODE    512
#define MTILE    32
#define NTHREADS 256
#define EPSF     1e-6f

#define XSS  136   // xs row stride (halves)
#define CB1S 40    // GEMM1 cb k-slice row stride (32 k + pad)
#define CB2S 136   // GEMM2 cb chunk row stride
#define PSS  520   // P row stride

// half-offsets in dynamic smem
#define XS_H 0
#define XS_L 4352
#define CB1H 8704
#define CB1L 29184     // end 49664
#define P16H 0
#define P16L 16640     // end 33280
#define CB2H 33280
#define CB2L 41984     // end 50688
#define SCR  50688     // 1024 floats scratch (2048 halves)
#define SMEM_HALVES (SCR + 2048)
#define SMEM_BYTES  (SMEM_HALVES * 2)

__device__ __half cbh_g[NCODE * DIMX];
__device__ __half cbl_g[NCODE * DIMX];

__device__ __forceinline__ void split2(float v, __half& h, __half& l) {
    h = __float2half_rn(v);
    l = __float2half_rn(v - __half2float(h));
}

__device__ __forceinline__ void mma16(float* d,
                                      uint32_t a0, uint32_t a1, uint32_t a2, uint32_t a3,
                                      uint32_t b0, uint32_t b1) {
    asm volatile(
        "mma.sync.aligned.m16n8k16.row.col.f32.f16.f16.f32 "
        "{%0,%1,%2,%3},{%4,%5,%6,%7},{%8,%9},{%0,%1,%2,%3};"
        : "+f"(d[0]), "+f"(d[1]), "+f"(d[2]), "+f"(d[3])
        : "r"(a0), "r"(a1), "r"(a2), "r"(a3), "r"(b0), "r"(b1));
}

__device__ __forceinline__ void ldsm_x4(uint32_t& r0, uint32_t& r1, uint32_t& r2, uint32_t& r3,
                                        uint32_t addr) {
    asm volatile("ldmatrix.sync.aligned.m8n8.x4.shared.b16 {%0,%1,%2,%3},[%4];"
                 : "=r"(r0), "=r"(r1), "=r"(r2), "=r"(r3) : "r"(addr));
}
__device__ __forceinline__ void ldsm_x4t(uint32_t& r0, uint32_t& r1, uint32_t& r2, uint32_t& r3,
                                         uint32_t addr) {
    asm volatile("ldmatrix.sync.aligned.m8n8.x4.trans.shared.b16 {%0,%1,%2,%3},[%4];"
                 : "=r"(r0), "=r"(r1), "=r"(r2), "=r"(r3) : "r"(addr));
}
__device__ __forceinline__ void cp16(uint32_t dst, const void* src) {
    asm volatile("cp.async.cg.shared.global [%0], [%1], 16;" :: "r"(dst), "l"(src));
}
__device__ __forceinline__ void cp_commit() {
    asm volatile("cp.async.commit_group;" ::: "memory");
}
__device__ __forceinline__ void cp_wait_all() {
    asm volatile("cp.async.wait_group 0;" ::: "memory");
}

__global__ void cb_split_kernel(const float* __restrict__ cb) {
    int i = (blockIdx.x * 256 + threadIdx.x) * 4;
    float4 v = *(const float4*)(cb + i);
    __half h0, l0, h1, l1, h2, l2, h3, l3;
    split2(v.x, h0, l0); split2(v.y, h1, l1);
    split2(v.z, h2, l2); split2(v.w, h3, l3);
    *(half2*)(cbh_g + i)     = __halves2half2(h0, h1);
    *(half2*)(cbh_g + i + 2) = __halves2half2(h2, h3);
    *(half2*)(cbl_g + i)     = __halves2half2(l0, l1);
    *(half2*)(cbl_g + i + 2) = __halves2half2(l2, l3);
}

__global__ __launch_bounds__(NTHREADS, 2)
void gvq_main(const float* __restrict__ x,
              const float* __restrict__ mask,
              const float* __restrict__ noise,
              float* __restrict__ q_out,
              float* __restrict__ enc_out,
              float* __restrict__ idx_out)
{
    extern __shared__ __half sm[];
    __half* xs_h = sm + XS_H;
    __half* xs_l = sm + XS_L;
    __half* p16h = sm + P16H;
    __half* p16l = sm + P16L;
    float*  scrf = (float*)(sm + SCR);
    float* redD = scrf;
    float* redI = scrf + 256;
    float* redM = scrf + 512;
    float* redS = scrf + 768;

    const int tid  = threadIdx.x;
    const int wid  = tid >> 5;
    const int lane = tid & 31;
    const int lq   = lane >> 2;
    const int lr   = lane & 3;
    const int row0 = blockIdx.x * MTILE;
    const int wk   = wid >> 2;   // GEMM2: k-half
    const int wn   = wid & 3;    // GEMM2: n32 group

    const uint32_t smem_u32 = (uint32_t)__cvta_generic_to_shared(sm);

    // ---- issue GEMM1 k-slice 0 staging (overlaps Phase A) ----
    {
        const int kk = 0;
        #pragma unroll
        for (int j = 0; j < 8; j++) {
            int f = tid + 256 * j;
            int code = f >> 2, q = f & 3;
            cp16(smem_u32 + (CB1H + code * CB1S + q * 8) * 2,
                 cbh_g + code * DIMX + kk * 32 + q * 8);
            cp16(smem_u32 + (CB1L + code * CB1S + q * 8) * 2,
                 cbl_g + code * DIMX + kk * 32 + q * 8);
        }
        cp_commit();
    }

    // ================= Phase A: load x, nudge, normalize, split =================
    {
        int arow = wid * 4 + (lane >> 3);
        int u    = lane & 7;
        float mv = mask[row0 + arow];
        float nudge = (1.0f - mv) * EPSF;
        const float4* xp = (const float4*)(x + (size_t)(row0 + arow) * DIMX + u * 16);
        float v[16];
        float acc = 0.0f;
        #pragma unroll
        for (int j = 0; j < 4; j++) {
            float4 t = xp[j];
            v[4*j+0] = t.x + nudge; v[4*j+1] = t.y + nudge;
            v[4*j+2] = t.z + nudge; v[4*j+3] = t.w + nudge;
        }
        #pragma unroll
        for (int j = 0; j < 16; j++) acc += v[j] * v[j];
        acc += __shfl_xor_sync(0xffffffffu, acc, 1);
        acc += __shfl_xor_sync(0xffffffffu, acc, 2);
        acc += __shfl_xor_sync(0xffffffffu, acc, 4);
        float nr = fmaxf(sqrtf(acc), EPSF);
        #pragma unroll
        for (int j = 0; j < 8; j++) {
            float a0 = v[2*j]   / nr;
            float a1 = v[2*j+1] / nr;
            __half h0, l0, h1, l1;
            split2(a0, h0, l0);
            split2(a1, h1, l1);
            *(half2*)&xs_h[arow * XSS + u * 16 + 2*j] = __halves2half2(h0, h1);
            *(half2*)&xs_l[arow * XSS + u * 16 + 2*j] = __halves2half2(l0, l1);
        }
    }
    cp_wait_all();
    __syncthreads();

    // ================= GEMM1: scores = Xn @ CB^T  (warp tile m32 x n64) =================
    float s[2][8][4];
    #pragma unroll
    for (int mf = 0; mf < 2; mf++)
        #pragma unroll
        for (int nf = 0; nf < 8; nf++)
            #pragma unroll
            for (int e = 0; e < 4; e++)
                s[mf][nf][e] = 0.0f;

    const uint32_t a1h = smem_u32 + (XS_H + (lane & 15) * XSS + (lane >> 4) * 8) * 2;
    const uint32_t a1l = a1h + (XS_L - XS_H) * 2;
    const uint32_t b1  = smem_u32 + (CB1H +
        (wid * 64 + (lane & 7) + ((lane >> 4) & 1) * 8) * CB1S + ((lane >> 3) & 1) * 8) * 2;
    const uint32_t b1l_d = (CB1L - CB1H) * 2;

    for (int kk = 0; kk < 4; kk++) {
        #pragma unroll
        for (int k16 = 0; k16 < 2; k16++) {
            uint32_t acol = (kk * 32 + k16 * 16) * 2;
            uint32_t ah[8], al[8];
            ldsm_x4(ah[0], ah[1], ah[2], ah[3], a1h + acol);
            ldsm_x4(ah[4], ah[5], ah[6], ah[7], a1h + acol + 16 * XSS * 2);
            ldsm_x4(al[0], al[1], al[2], al[3], a1l + acol);
            ldsm_x4(al[4], al[5], al[6], al[7], a1l + acol + 16 * XSS * 2);
            #pragma unroll
            for (int nf4 = 0; nf4 < 4; nf4++) {
                uint32_t baddr = b1 + nf4 * (16 * CB1S * 2) + k16 * 32;
                uint32_t bh0, bh1, bh2, bh3, bl0, bl1, bl2, bl3;
                ldsm_x4(bh0, bh1, bh2, bh3, baddr);
                ldsm_x4(bl0, bl1, bl2, bl3, baddr + b1l_d);
                #pragma unroll
                for (int mf = 0; mf < 2; mf++) {
                    float* d0 = s[mf][nf4 * 2 + 0];
                    float* d1 = s[mf][nf4 * 2 + 1];
                    mma16(d0, ah[mf*4+0], ah[mf*4+1], ah[mf*4+2], ah[mf*4+3], bh0, bh1);
                    mma16(d0, ah[mf*4+0], ah[mf*4+1], ah[mf*4+2], ah[mf*4+3], bl0, bl1);
                    mma16(d0, al[mf*4+0], al[mf*4+1], al[mf*4+2], al[mf*4+3], bh0, bh1);
                    mma16(d1, ah[mf*4+0], ah[mf*4+1], ah[mf*4+2], ah[mf*4+3], bh2, bh3);
                    mma16(d1, ah[mf*4+0], ah[mf*4+1], ah[mf*4+2], ah[mf*4+3], bl2, bl3);
                    mma16(d1, al[mf*4+0], al[mf*4+1], al[mf*4+2], al[mf*4+3], bh2, bh3);
                }
            }
        }
        __syncthreads();
        if (kk < 3) {   // stage next k-slice
            int nk = kk + 1;
            #pragma unroll
            for (int j = 0; j < 8; j++) {
                int f = tid + 256 * j;
                int code = f >> 2, q = f & 3;
                cp16(smem_u32 + (CB1H + code * CB1S + q * 8) * 2,
                     cbh_g + code * DIMX + nk * 32 + q * 8);
                cp16(smem_u32 + (CB1L + code * CB1S + q * 8) * 2,
                     cbl_g + code * DIMX + nk * 32 + q * 8);
            }
            cp_commit();
            cp_wait_all();
            __syncthreads();
        }
    }

    // ================= Phase C: distances -> argmin -> gumbel softmax =================
    float mind[4], maxl[4], sums[4], invs[4];
    int   mini[4];
    #pragma unroll
    for (int rs = 0; rs < 4; rs++) {
        mind[rs] = 3.402823466e+38f;
        mini[rs] = 0;
        maxl[rs] = -3.402823466e+38f;
    }

    #pragma unroll
    for (int mf = 0; mf < 2; mf++) {
        #pragma unroll
        for (int eh = 0; eh < 2; eh++) {
            int rs = mf * 2 + eh;
            int grow = row0 + mf * 16 + eh * 8 + lq;
            const float* np = noise + (size_t)grow * NCODE + wid * 64 + 2 * lr;
            #pragma unroll
            for (int nf = 0; nf < 8; nf++) {
                float2 nz = *(const float2*)(np + nf * 8);
                float ab0 = s[mf][nf][eh * 2];
                float ab1 = s[mf][nf][eh * 2 + 1];
                float d0 = (1.0f - 2.0f * ab0) + 1.0f;
                float d1 = (1.0f - 2.0f * ab1) + 1.0f;
                int c0 = wid * 64 + nf * 8 + 2 * lr;
                if (d0 < mind[rs]) { mind[rs] = d0; mini[rs] = c0; }
                if (d1 < mind[rs]) { mind[rs] = d1; mini[rs] = c0 + 1; }
                float l0 = nz.x - d0;
                float l1 = nz.y - d1;
                maxl[rs] = fmaxf(maxl[rs], fmaxf(l0, l1));
                s[mf][nf][eh * 2]     = l0;
                s[mf][nf][eh * 2 + 1] = l1;
            }
        }
    }
    #pragma unroll
    for (int rs = 0; rs < 4; rs++) {
        #pragma unroll
        for (int off = 1; off < 4; off <<= 1) {
            float od = __shfl_xor_sync(0xffffffffu, mind[rs], off);
            int   oi = __shfl_xor_sync(0xffffffffu, mini[rs], off);
            if (od < mind[rs] || (od == mind[rs] && oi < mini[rs])) { mind[rs] = od; mini[rs] = oi; }
            maxl[rs] = fmaxf(maxl[rs], __shfl_xor_sync(0xffffffffu, maxl[rs], off));
        }
    }
    if (lr == 0) {
        #pragma unroll
        for (int rs = 0; rs < 4; rs++) {
            int row = (rs >> 1) * 16 + (rs & 1) * 8 + lq;
            redD[row * 8 + wid] = mind[rs];
            redI[row * 8 + wid] = (float)mini[rs];
            redM[row * 8 + wid] = maxl[rs];
        }
    }
    __syncthreads();
    #pragma unroll
    for (int rs = 0; rs < 4; rs++) {
        int row = (rs >> 1) * 16 + (rs & 1) * 8 + lq;
        float gd = redD[row * 8 + 0];
        int   gi = (int)redI[row * 8 + 0];
        float gm = redM[row * 8 + 0];
        #pragma unroll
        for (int w = 1; w < 8; w++) {
            float od = redD[row * 8 + w];
            int   oi = (int)redI[row * 8 + w];
            if (od < gd || (od == gd && oi < gi)) { gd = od; gi = oi; }
            gm = fmaxf(gm, redM[row * 8 + w]);
        }
        mini[rs] = gi;
        maxl[rs] = gm;
        sums[rs] = 0.0f;
    }
    #pragma unroll
    for (int mf = 0; mf < 2; mf++)
        #pragma unroll
        for (int eh = 0; eh < 2; eh++) {
            int rs = mf * 2 + eh;
            #pragma unroll
            for (int nf = 0; nf < 8; nf++) {
                float e0 = __expf(s[mf][nf][eh * 2]     - maxl[rs]);
                float e1 = __expf(s[mf][nf][eh * 2 + 1] - maxl[rs]);
                s[mf][nf][eh * 2]     = e0;
                s[mf][nf][eh * 2 + 1] = e1;
                sums[rs] += e0 + e1;
            }
        }
    #pragma unroll
    for (int rs = 0; rs < 4; rs++) {
        sums[rs] += __shfl_xor_sync(0xffffffffu, sums[rs], 1);
        sums[rs] += __shfl_xor_sync(0xffffffffu, sums[rs], 2);
    }
    if (lr == 0) {
        #pragma unroll
        for (int rs = 0; rs < 4; rs++) {
            int row = (rs >> 1) * 16 + (rs & 1) * 8 + lq;
            redS[row * 8 + wid] = sums[rs];
        }
    }
    __syncthreads();
    #pragma unroll
    for (int rs = 0; rs < 4; rs++) {
        int row = (rs >> 1) * 16 + (rs & 1) * 8 + lq;
        float t = 0.0f;
        #pragma unroll
        for (int w = 0; w < 8; w++) t += redS[row * 8 + w];
        invs[rs] = 1.0f / t;
    }

    // ---- issue GEMM2 chunk-0 staging (overlaps P/enc writes; cb1 is dead) ----
    {
        const int c = 0;
        #pragma unroll
        for (int j = 0; j < 4; j++) {
            int f = tid + 256 * j;
            int r = f >> 4, q = f & 15;
            int wk2 = r >> 5, ci = r & 31;
            const __half* sh = cbh_g + (size_t)(wk2 * 256 + c * 32 + ci) * DIMX + q * 8;
            const __half* sl = cbl_g + (size_t)(wk2 * 256 + c * 32 + ci) * DIMX + q * 8;
            cp16(smem_u32 + (CB2H + r * CB2S + q * 8) * 2, sh);
            cp16(smem_u32 + (CB2L + r * CB2S + q * 8) * 2, sl);
        }
        cp_commit();
    }

    // probs -> p16 smem + enc_out; indices
    #pragma unroll
    for (int mf = 0; mf < 2; mf++)
        #pragma unroll
        for (int eh = 0; eh < 2; eh++) {
            int rs = mf * 2 + eh;
            int row = mf * 16 + eh * 8 + lq;
            float* ep = enc_out + (size_t)(row0 + row) * NCODE + wid * 64 + 2 * lr;
            #pragma unroll
            for (int nf = 0; nf < 8; nf++) {
                float p0 = s[mf][nf][eh * 2]     * invs[rs];
                float p1 = s[mf][nf][eh * 2 + 1] * invs[rs];
                __half h0, l0, h1, l1;
                split2(p0, h0, l0);
                split2(p1, h1, l1);
                int col = wid * 64 + nf * 8 + 2 * lr;
                *(half2*)&p16h[row * PSS + col] = __halves2half2(h0, h1);
                *(half2*)&p16l[row * PSS + col] = __halves2half2(l0, l1);
                *(float2*)(ep + nf * 8) = make_float2(p0, p1);
            }
        }
    if (wid == 0 && lr == 0) {
        #pragma unroll
        for (int rs = 0; rs < 4; rs++) {
            int row = (rs >> 1) * 16 + (rs & 1) * 8 + lq;
            idx_out[row0 + row] = (float)mini[rs];
        }
    }
    __syncthreads();

    // ================= GEMM2: Q = P @ CB  (split-k, warp tile m32 x n32) =================
    float q[2][4][4];
    #pragma unroll
    for (int mf = 0; mf < 2; mf++)
        #pragma unroll
        for (int nf = 0; nf < 4; nf++)
            #pragma unroll
            for (int e = 0; e < 4; e++)
                q[mf][nf][e] = 0.0f;

    const uint32_t a2h = smem_u32 + (P16H + (lane & 15) * PSS + (lane >> 4) * 8) * 2;
    const uint32_t a2l = a2h + (P16L - P16H) * 2;
    const uint32_t b2  = smem_u32 + (CB2H +
        (wk * 32 + (lane & 15)) * CB2S + wn * 32 + (lane >> 4) * 8) * 2;
    const uint32_t b2l_d = (CB2L - CB2H) * 2;

    for (int c = 0; c < 8; c++) {
        cp_wait_all();
        __syncthreads();
        #pragma unroll
        for (int k16 = 0; k16 < 2; k16++) {
            uint32_t acol = (uint32_t)(wk * 256 + c * 32 + k16 * 16) * 2;
            uint32_t ah[8], al[8];
            ldsm_x4(ah[0], ah[1], ah[2], ah[3], a2h + acol);
            ldsm_x4(ah[4], ah[5], ah[6], ah[7], a2h + acol + 16 * PSS * 2);
            ldsm_x4(al[0], al[1], al[2], al[3], a2l + acol);
            ldsm_x4(al[4], al[5], al[6], al[7], a2l + acol + 16 * PSS * 2);
            #pragma unroll
            for (int nf2 = 0; nf2 < 2; nf2++) {
                uint32_t baddr = b2 + k16 * (16 * CB2S * 2) + nf2 * 32;
                uint32_t bh0, bh1, bh2, bh3, bl0, bl1, bl2, bl3;
                ldsm_x4t(bh0, bh1, bh2, bh3, baddr);
                ldsm_x4t(bl0, bl1, bl2, bl3, baddr + b2l_d);
                #pragma unroll
                for (int mf = 0; mf < 2; mf++) {
                    float* d0 = q[mf][nf2 * 2 + 0];
                    float* d1 = q[mf][nf2 * 2 + 1];
                    mma16(d0, ah[mf*4+0], ah[mf*4+1], ah[mf*4+2], ah[mf*4+3], bh0, bh1);
                    mma16(d0, ah[mf*4+0], ah[mf*4+1], ah[mf*4+2], ah[mf*4+3], bl0, bl1);
                    mma16(d0, al[mf*4+0], al[mf*4+1], al[mf*4+2], al[mf*4+3], bh0, bh1);
                    mma16(d1, ah[mf*4+0], ah[mf*4+1], ah[mf*4+2], ah[mf*4+3], bh2, bh3);
                    mma16(d1, ah[mf*4+0], ah[mf*4+1], ah[mf*4+2], ah[mf*4+3], bl2, bl3);
                    mma16(d1, al[mf*4+0], al[mf*4+1], al[mf*4+2], al[mf*4+3], bh2, bh3);
                }
            }
        }
        __syncthreads();
        if (c < 7) {
            int nc = c + 1;
            #pragma unroll
            for (int j = 0; j < 4; j++) {
                int f = tid + 256 * j;
                int r = f >> 4, qq = f & 15;
                int wk2 = r >> 5, ci = r & 31;
                const __half* sh = cbh_g + (size_t)(wk2 * 256 + nc * 32 + ci) * DIMX + qq * 8;
                const __half* sl = cbl_g + (size_t)(wk2 * 256 + nc * 32 + ci) * DIMX + qq * 8;
                cp16(smem_u32 + (CB2H + r * CB2S + qq * 8) * 2, sh);
                cp16(smem_u32 + (CB2L + r * CB2S + qq * 8) * 2, sl);
            }
            cp_commit();
        }
    }

    // split-k reduction (qred aliases dead cb2 region)
    float* qred = (float*)(sm + CB2H);
    if (wk == 1) {
        #pragma unroll
        for (int mf = 0; mf < 2; mf++)
            #pragma unroll
            for (int nf = 0; nf < 4; nf++)
                #pragma unroll
                for (int e = 0; e < 4; e++) {
                    int row = mf * 16 + lq + (e >> 1) * 8;
                    int col = wn * 32 + nf * 8 + 2 * lr + (e & 1);
                    qred[row * 132 + col] = q[mf][nf][e];
                }
    }
    __syncthreads();
    if (wk == 0) {
        #pragma unroll
        for (int mf = 0; mf < 2; mf++)
            #pragma unroll
            for (int nf = 0; nf < 4; nf++)
                #pragma unroll
                for (int eh = 0; eh < 2; eh++) {
                    int row  = mf * 16 + lq + eh * 8;
                    int col0 = wn * 32 + nf * 8 + 2 * lr;
                    float v0 = q[mf][nf][eh * 2]     + qred[row * 132 + col0];
                    float v1 = q[mf][nf][eh * 2 + 1] + qred[row * 132 + col0 + 1];
                    *(float2*)(q_out + (size_t)(row0 + row) * DIMX + col0)
                        = make_float2(v0, v1);
                }
    }
}

extern "C" void kernel_launch(void* const* d_in, const int* in_sizes, int n_in,
                              void* d_out, int out_size)
{
    const float* x        = (const float*)d_in[0];
    const float* mask     = (const float*)d_in[1];
    const float* codebook = (const float*)d_in[2];
    const float* noise    = (const float*)d_in[3];

    const int n = in_sizes[0] / DIMX;   // 131072

    float* q_out   = (float*)d_out;
    float* enc_out = q_out + (size_t)n * DIMX;
    float* idx_out = enc_out + (size_t)n * NCODE;

    cb_split_kernel<<<NCODE * DIMX / 1024, 256>>>(codebook);

    cudaFuncSetAttribute(gvq_main,
                         cudaFuncAttributeMaxDynamicSharedMemorySize,
                         SMEM_BYTES);
    gvq_main<<<n / MTILE, NTHREADS, SMEM_BYTES>>>(
        x, mask, noise, q_out, enc_out, idx_out);
}